// round 4
// baseline (speedup 1.0000x reference)
#include <cuda_runtime.h>
#include <cuda_bf16.h>

// AttentionLayer: out[b,u] = sum_t softmax_t(tanh(x[b,t,:]·W + b[t])) * x[b,t,u]
// B=256, T=2048, U=512, fp32. Single fused HBM pass (tanh in (-1,1) => exp safe
// without max-subtraction). R3: software-pipelined row loads (double buffer) so
// LDGs stay in flight across the dot/shfl/tanh/exp chain; W moved to shared to
// fit the 64-reg cap; __ldcs streaming loads; interleaved row->warp mapping.

#define T_DIM 2048
#define U_DIM 512
#define NWARP 16
#define TPW   (T_DIM / NWARP)   // 128 timesteps per warp

__global__ __launch_bounds__(512, 2)
void attn_pool_kernel(const float* __restrict__ x,
                      const float* __restrict__ W,
                      const float* __restrict__ bvec,
                      float* __restrict__ out)
{
    __shared__ float  sacc[NWARP * U_DIM];   // 32 KB: per-warp partial accumulators
    __shared__ float  ssum[NWARP];           // per-warp partial denominators
    __shared__ float4 sW[U_DIM / 4];         // 2 KB: W kept in smem (frees 16 regs)

    const int batch = blockIdx.x;
    const int tid   = threadIdx.x;
    const int warp  = tid >> 5;
    const int lane  = tid & 31;

    if (tid < U_DIM / 4)
        sW[tid] = reinterpret_cast<const float4*>(W)[tid];
    __syncthreads();

    float4 acc[4];
#pragma unroll
    for (int c = 0; c < 4; c++)
        acc[c] = make_float4(0.f, 0.f, 0.f, 0.f);
    float s = 0.f;

    const float4* xb = reinterpret_cast<const float4*>(
        x + (size_t)batch * T_DIM * U_DIM);

    // Interleaved mapping: warp w handles rows t = w, w+16, w+32, ...
    // => the CTA's 16 warps form one contiguous moving window over memory.
    float4 xv0[4], xv1[4];
    int t0 = warp;

    // Prologue: load first row into buffer 0.
#pragma unroll
    for (int c = 0; c < 4; c++)
        xv0[c] = __ldcs(&xb[(size_t)t0 * 128 + c * 32 + lane]);

#define PROCESS(XV, TT)                                                     \
    do {                                                                    \
        float p = 0.f;                                                      \
        _Pragma("unroll")                                                   \
        for (int c = 0; c < 4; c++) {                                       \
            const float4 wv = sW[c * 32 + lane];                            \
            p += XV[c].x * wv.x + XV[c].y * wv.y                            \
               + XV[c].z * wv.z + XV[c].w * wv.w;                           \
        }                                                                   \
        _Pragma("unroll")                                                   \
        for (int o = 16; o > 0; o >>= 1)                                    \
            p += __shfl_xor_sync(0xffffffffu, p, o);                        \
        const float e = tanhf(p + __ldg(&bvec[TT]));                        \
        const float w = __expf(e);  /* safe: e in (-1,1) */                 \
        s += w;                                                             \
        _Pragma("unroll")                                                   \
        for (int c = 0; c < 4; c++) {                                       \
            acc[c].x += w * XV[c].x;                                        \
            acc[c].y += w * XV[c].y;                                        \
            acc[c].z += w * XV[c].z;                                        \
            acc[c].w += w * XV[c].w;                                        \
        }                                                                   \
    } while (0)

    for (int i = 0; i < TPW; i += 2) {
        const int t1 = t0 + NWARP;
        // Prefetch row t1 into buffer 1, then process buffer 0 (row t0).
#pragma unroll
        for (int c = 0; c < 4; c++)
            xv1[c] = __ldcs(&xb[(size_t)t1 * 128 + c * 32 + lane]);

        PROCESS(xv0, t0);

        // Prefetch row t2 into buffer 0 (clamped re-read on last iteration to
        // avoid OOB; the redundant load result is simply overwritten next pass).
        const int t2 = (i + 2 < TPW) ? (t1 + NWARP) : t0;
#pragma unroll
        for (int c = 0; c < 4; c++)
            xv0[c] = __ldcs(&xb[(size_t)t2 * 128 + c * 32 + lane]);

        PROCESS(xv1, t1);

        t0 = t1 + NWARP;
    }
#undef PROCESS

    // Stash per-warp partials in shared memory.
#pragma unroll
    for (int c = 0; c < 4; c++)
        reinterpret_cast<float4*>(sacc + warp * U_DIM)[c * 32 + lane] = acc[c];
    if (lane == 0) ssum[warp] = s;
    __syncthreads();

    // Cross-warp reduction: thread `tid` owns output element u = tid (0..511).
    float stot = 0.f;
#pragma unroll
    for (int w_ = 0; w_ < NWARP; w_++) stot += ssum[w_];
    const float inv = 1.0f / stot;

    float v = 0.f;
#pragma unroll
    for (int w_ = 0; w_ < NWARP; w_++)
        v += sacc[w_ * U_DIM + tid];        // conflict-free: consecutive tids
    out[(size_t)batch * U_DIM + tid] = v * inv;
}

extern "C" void kernel_launch(void* const* d_in, const int* in_sizes, int n_in,
                              void* d_out, int out_size)
{
    const float* x  = (const float*)d_in[0];   // (256, 2048, 512) f32
    const float* W  = (const float*)d_in[1];   // (512, 1) f32
    const float* bv = (const float*)d_in[2];   // (2048, 1) f32
    float* out = (float*)d_out;                // (256, 512) f32

    attn_pool_kernel<<<256, 512>>>(x, W, bv, out);
}

// round 5
// speedup vs baseline: 1.3386x; 1.3386x over previous
#include <cuda_runtime.h>
#include <cuda_bf16.h>

// AttentionLayer: out[b,u] = sum_t softmax_t(tanh(x[b,t,:]·W + b[t])) * x[b,t,u]
// B=256, T=2048, U=512, fp32. Single fused HBM pass (tanh in (-1,1) => exp safe
// without max-subtraction).
// R4: R2 structure (no register double-buffer -- R3 proved it spills at the
// 64-reg cap) + zero-register L2 prefetch of the next row to cover the
// dot->shfl->tanh->exp dependency chain.

#define T_DIM 2048
#define U_DIM 512
#define NWARP 16
#define TPW   (T_DIM / NWARP)   // 128 timesteps per warp

__device__ __forceinline__ void prefetch_l2(const void* p) {
    asm volatile("prefetch.global.L2 [%0];" :: "l"(p));
}

__global__ __launch_bounds__(512, 2)
void attn_pool_kernel(const float* __restrict__ x,
                      const float* __restrict__ W,
                      const float* __restrict__ bvec,
                      float* __restrict__ out)
{
    __shared__ float sacc[NWARP * U_DIM];   // 32 KB: per-warp partial accumulators
    __shared__ float ssum[NWARP];           // per-warp partial softmax denominators

    const int batch = blockIdx.x;
    const int tid   = threadIdx.x;
    const int warp  = tid >> 5;
    const int lane  = tid & 31;

    // Per-lane W slice: lane holds u = c*128 + lane*4 + {0..3}, c = 0..3
    float4 wv[4];
#pragma unroll
    for (int c = 0; c < 4; c++)
        wv[c] = reinterpret_cast<const float4*>(W)[c * 32 + lane];

    float4 acc[4];
#pragma unroll
    for (int c = 0; c < 4; c++)
        acc[c] = make_float4(0.f, 0.f, 0.f, 0.f);
    float s = 0.f;

    const float4* xb = reinterpret_cast<const float4*>(
        x + (size_t)batch * T_DIM * U_DIM);

    const int t0 = warp * TPW;   // contiguous timestep slab per warp

    for (int i = 0; i < TPW; i++) {
        const int t = t0 + i;
        const float4* rowp = xb + (size_t)t * 128 + lane;

        // Load full 512-float row across the warp: 4x float4 per lane, coalesced.
        float4 xv[4];
#pragma unroll
        for (int c = 0; c < 4; c++)
            xv[c] = rowp[c * 32];

        // Zero-register-cost prefetch of the NEXT row into L2: same lane
        // addresses + 2048 bytes ([R+imm] addressing). Keeps DRAM streaming
        // while this warp sits in the dependent compute chain below.
        if (i + 1 < TPW) {
#pragma unroll
            for (int c = 0; c < 4; c++)
                prefetch_l2(rowp + c * 32 + 128);
        }

        // Partial dot with W
        float p = 0.f;
#pragma unroll
        for (int c = 0; c < 4; c++)
            p += xv[c].x * wv[c].x + xv[c].y * wv[c].y
               + xv[c].z * wv[c].z + xv[c].w * wv[c].w;

        // Warp-wide reduction (butterfly -> every lane has full dot)
#pragma unroll
        for (int o = 16; o > 0; o >>= 1)
            p += __shfl_xor_sync(0xffffffffu, p, o);

        const float e = tanhf(p + bvec[t]);
        const float w = __expf(e);           // safe: e in (-1,1)
        s += w;

        // Accumulate weighted row while xv is still in registers
#pragma unroll
        for (int c = 0; c < 4; c++) {
            acc[c].x += w * xv[c].x;
            acc[c].y += w * xv[c].y;
            acc[c].z += w * xv[c].z;
            acc[c].w += w * xv[c].w;
        }
    }

    // Stash per-warp partials in shared memory
#pragma unroll
    for (int c = 0; c < 4; c++)
        reinterpret_cast<float4*>(sacc + warp * U_DIM)[c * 32 + lane] = acc[c];
    if (lane == 0) ssum[warp] = s;
    __syncthreads();

    // Cross-warp reduction: thread `tid` owns output element u = tid (0..511)
    float stot = 0.f;
#pragma unroll
    for (int w_ = 0; w_ < NWARP; w_++) stot += ssum[w_];
    const float inv = 1.0f / stot;

    float v = 0.f;
#pragma unroll
    for (int w_ = 0; w_ < NWARP; w_++)
        v += sacc[w_ * U_DIM + tid];        // conflict-free: consecutive tids

    out[(size_t)batch * U_DIM + tid] = v * inv;
}

extern "C" void kernel_launch(void* const* d_in, const int* in_sizes, int n_in,
                              void* d_out, int out_size)
{
    const float* x  = (const float*)d_in[0];   // (256, 2048, 512) f32
    const float* W  = (const float*)d_in[1];   // (512, 1) f32
    const float* bv = (const float*)d_in[2];   // (2048, 1) f32
    float* out = (float*)d_out;                // (256, 512) f32

    attn_pool_kernel<<<256, 512>>>(x, W, bv, out);
}